// round 8
// baseline (speedup 1.0000x reference)
#include <cuda_runtime.h>
#include <math.h>

// ---------------------------------------------------------------------------
// Problem dims (fixed)
// ---------------------------------------------------------------------------
static constexpr int B_  = 128;
static constexpr int T_  = 512;
static constexpr int H_  = 256;          // lstm hidden
static constexpr int H2_ = 512;          // encoder width
static constexpr int LIN_ = 200;
static constexpr int PD_ = 50, WD_ = 20;
static constexpr int F_  = PD_ + H2_ + WD_;   // 582
static constexpr int G4_ = 4 * H_;            // 1024
static constexpr int SP_ = 58;
static constexpr int KC_ = H_ + H2_;          // 768 (combine K)
static constexpr int M_  = B_ * T_;           // 65536

// ---------------------------------------------------------------------------
// Scratch (device globals: no allocations allowed)
// ---------------------------------------------------------------------------
__device__ float g_feats[(size_t)M_ * F_];    // [B*T, 582]
__device__ float g_z[(size_t)M_ * LIN_];      // [B*T, 200]
__device__ float g_xg[(size_t)M_ * G4_];      // [B*T, 1024]  z@W_ih^T + b_ih + b_hh
__device__ float g_hs[(size_t)M_ * H_];       // [B*T, 256]   LSTM outputs
__device__ float g_h[2 * B_ * H_];            // double-buffered h state
__device__ unsigned g_bar;                    // grid barrier counter

// ---------------------------------------------------------------------------
// 1) Feature construction: streaming per-batch scan.
//    Thread c owns channel c; scalar sep/pos recurrence replicated per thread.
// ---------------------------------------------------------------------------
__global__ void feats_kernel(const float* __restrict__ enc, const int* __restrict__ sep,
                             const int* __restrict__ pos, const float* __restrict__ pemb,
                             const float* __restrict__ wemb)
{
    int b = blockIdx.x;
    int c = threadIdx.x;                 // 0..511
    float S = 0.f, snap = 0.f;           // csum[t], csum[last_sep]
    int last_sep = 0;
    int lp = pos[b * T_];                // pos_ids[b, last_sep=0]
    for (int t = 0; t < T_; t++) {
        int wlen = t - last_sep;
        int ws = wlen < 1 ? 1 : wlen;
        int wid = ws > 7 ? 7 : ws;
        float inv = 1.f / (float)ws;
        size_t base = ((size_t)b * T_ + t) * F_;
        g_feats[base + PD_ + c] = (S - snap) * inv;                // word_avg
        if (c < PD_) g_feats[base + c] = pemb[lp * PD_ + c];       // pos emb
        if (c < WD_) g_feats[base + PD_ + H2_ + c] = wemb[wid * WD_ + c];
        int sm = sep[b * T_ + t];
        if (sm) { snap = S; last_sep = t; lp = pos[b * T_ + t]; }
        S += enc[((size_t)b * T_ + t) * H2_ + c];
    }
}

// ---------------------------------------------------------------------------
// fp32 GEMM-NT tiles: BM=64, BN=64, BK=16, 256 threads, 4x4 micro-tile.
// Three variants differing only in A-gather / epilogue.
// ---------------------------------------------------------------------------
__global__ __launch_bounds__(256) void gemm_fc(const float* __restrict__ W,
                                               const float* __restrict__ bias)
{
    __shared__ float As[16][65];
    __shared__ float Bs[16][65];
    int m0 = blockIdx.x * 64;
    int n0 = blockIdx.y * 64;
    int tid = threadIdx.x;
    int tx = tid & 15, ty = tid >> 4;
    float acc[4][4] = {};
    for (int k0 = 0; k0 < F_; k0 += 16) {
#pragma unroll
        for (int i = 0; i < 4; i++) {
            int e = tid + i * 256;
            int mm = e >> 4, kk = e & 15;
            int k = k0 + kk;
            As[kk][mm] = (k < F_) ? g_feats[(size_t)(m0 + mm) * F_ + k] : 0.f;
            int n = n0 + mm;
            Bs[kk][mm] = (n < LIN_ && k < F_) ? W[(size_t)n * F_ + k] : 0.f;
        }
        __syncthreads();
#pragma unroll
        for (int kk = 0; kk < 16; kk++) {
            float a[4], bb[4];
#pragma unroll
            for (int i = 0; i < 4; i++) a[i] = As[kk][ty * 4 + i];
#pragma unroll
            for (int j = 0; j < 4; j++) bb[j] = Bs[kk][tx * 4 + j];
#pragma unroll
            for (int i = 0; i < 4; i++)
#pragma unroll
                for (int j = 0; j < 4; j++)
                    acc[i][j] = fmaf(a[i], bb[j], acc[i][j]);
        }
        __syncthreads();
    }
#pragma unroll
    for (int i = 0; i < 4; i++) {
        int m = m0 + ty * 4 + i;
        int t = m & (T_ - 1);
#pragma unroll
        for (int j = 0; j < 4; j++) {
            int n = n0 + tx * 4 + j;
            if (n < LIN_) {
                float v = (t == 0) ? 0.f : tanhf(acc[i][j] + bias[n]);
                g_z[(size_t)m * LIN_ + n] = v;
            }
        }
    }
}

__global__ __launch_bounds__(256) void gemm_ih(const float* __restrict__ W,
                                               const float* __restrict__ bih,
                                               const float* __restrict__ bhh)
{
    __shared__ float As[16][65];
    __shared__ float Bs[16][65];
    int m0 = blockIdx.x * 64;
    int n0 = blockIdx.y * 64;
    int tid = threadIdx.x;
    int tx = tid & 15, ty = tid >> 4;
    float acc[4][4] = {};
    for (int k0 = 0; k0 < LIN_; k0 += 16) {
#pragma unroll
        for (int i = 0; i < 4; i++) {
            int e = tid + i * 256;
            int mm = e >> 4, kk = e & 15;
            int k = k0 + kk;
            As[kk][mm] = (k < LIN_) ? g_z[(size_t)(m0 + mm) * LIN_ + k] : 0.f;
            int n = n0 + mm;
            Bs[kk][mm] = (k < LIN_) ? W[(size_t)n * LIN_ + k] : 0.f;
        }
        __syncthreads();
#pragma unroll
        for (int kk = 0; kk < 16; kk++) {
            float a[4], bb[4];
#pragma unroll
            for (int i = 0; i < 4; i++) a[i] = As[kk][ty * 4 + i];
#pragma unroll
            for (int j = 0; j < 4; j++) bb[j] = Bs[kk][tx * 4 + j];
#pragma unroll
            for (int i = 0; i < 4; i++)
#pragma unroll
                for (int j = 0; j < 4; j++)
                    acc[i][j] = fmaf(a[i], bb[j], acc[i][j]);
        }
        __syncthreads();
    }
#pragma unroll
    for (int i = 0; i < 4; i++) {
        int m = m0 + ty * 4 + i;
#pragma unroll
        for (int j = 0; j < 4; j++) {
            int n = n0 + tx * 4 + j;
            g_xg[(size_t)m * G4_ + n] = acc[i][j] + bih[n] + bhh[n];
        }
    }
}

__global__ __launch_bounds__(256) void gemm_out(const float* __restrict__ enc,
                                                const float* __restrict__ Wc,
                                                const int* __restrict__ length,
                                                float* __restrict__ out)
{
    __shared__ float As[16][65];
    __shared__ float Bs[16][65];
    int m0 = blockIdx.x * 64;
    int tid = threadIdx.x;
    int tx = tid & 15, ty = tid >> 4;
    float acc[4][4] = {};
    for (int k0 = 0; k0 < KC_; k0 += 16) {
#pragma unroll
        for (int i = 0; i < 4; i++) {
            int e = tid + i * 256;
            int mm = e >> 4, kk = e & 15;
            int k = k0 + kk;
            int m = m0 + mm;
            float av;
            if (k < H_) av = g_hs[(size_t)m * H_ + k];
            else        av = enc[(size_t)m * H2_ + (k - H_)];
            As[kk][mm] = av;
            Bs[kk][mm] = (mm < SP_) ? Wc[(size_t)mm * KC_ + k] : 0.f;
        }
        __syncthreads();
#pragma unroll
        for (int kk = 0; kk < 16; kk++) {
            float a[4], bb[4];
#pragma unroll
            for (int i = 0; i < 4; i++) a[i] = As[kk][ty * 4 + i];
#pragma unroll
            for (int j = 0; j < 4; j++) bb[j] = Bs[kk][tx * 4 + j];
#pragma unroll
            for (int i = 0; i < 4; i++)
#pragma unroll
                for (int j = 0; j < 4; j++)
                    acc[i][j] = fmaf(a[i], bb[j], acc[i][j]);
        }
        __syncthreads();
    }
#pragma unroll
    for (int i = 0; i < 4; i++) {
        int m = m0 + ty * 4 + i;
        int b = m >> 9;
        int t = m & 511;
        int L = length[b];
#pragma unroll
        for (int j = 0; j < 4; j++) {
            int n = tx * 4 + j;
            if (n < SP_) {
                float v = acc[i][j];
                if (t == 0 && n == 0) v = -1e30f;   // forbid APP at t=0
                if (t >= L) v = 0.f;                // pad steps
                out[(size_t)m * SP_ + n] = v;
            }
        }
    }
}

// ---------------------------------------------------------------------------
// Init: zero h0 buffer and grid barrier (must happen every replay).
// ---------------------------------------------------------------------------
__global__ void init_kernel()
{
    int i = blockIdx.x * blockDim.x + threadIdx.x;
    if (i < B_ * H_) g_h[i] = 0.f;
    if (i == 0) g_bar = 0u;
}

// ---------------------------------------------------------------------------
// LSTM recurrence: single grid-resident kernel, 128 CTAs x 256 threads.
// CTA (bg, hg): 8 batches x 32 hidden units. W_hh slice float4-interleaved in
// smem (conflict-free LDS.128). h exchanged via double-buffered global (L2),
// loaded with __ldcg (L1 non-coherent across SMs). Counter spin barrier is
// safe: 143KB smem => 1 CTA/SM, grid 128 <= 148 SMs, all co-resident.
// ---------------------------------------------------------------------------
static constexpr int LSTM_SMEM_FLOATS = 4 * 32 * 256 + 8 * 256 + 8 * 4 * 32; // 35840
static constexpr int LSTM_SMEM_BYTES  = LSTM_SMEM_FLOATS * 4;                // 143360

__device__ __forceinline__ float sigm(float x) { return 1.f / (1.f + expf(-x)); }

__global__ __launch_bounds__(256, 1) void lstm_kernel(const float* __restrict__ Whh)
{
    extern __shared__ float smx[];
    float* Wint = smx;                         // 32768 floats (4g x 64k4 x 32u x 4)
    float* Hsm  = smx + 4 * 32 * 256;          // 2048 floats  (8b x 256)
    float* Gsm  = Hsm + 8 * 256;               // 1024 floats  (8b x 4g x 32u)
    float4* Hsm4 = (float4*)Hsm;
    const float4* W4 = (const float4*)Wint;

    int cid = blockIdx.x;
    int bg = cid >> 3;        // 0..15 (8 batches each)
    int hg = cid & 7;         // 0..7  (32 units each)
    int tid = threadIdx.x;
    int u  = tid & 31;
    int bp = (tid >> 5) & 3;  // batch pair
    int gp = tid >> 7;        // gate pair: 0 -> {i,f}, 1 -> {g,o}

    // Stage W_hh slice into smem, float4-interleaved over k.
    for (int e = tid; e < 4 * 32 * 256; e += 256) {
        int g = e >> 13;
        int rem = e & 8191;
        int u2 = rem >> 8;
        int k = rem & 255;
        int row = g * H_ + hg * 32 + u2;
        Wint[((g * 64 + (k >> 2)) * 32 + u2) * 4 + (k & 3)] = Whh[(size_t)row * H_ + k];
    }
    __syncthreads();

    int g0 = 2 * gp, g1 = g0 + 1;
    int b0 = 2 * bp, b1 = b0 + 1;
    const float4* Wb0 = W4 + (size_t)(g0 * 64) * 32 + u;
    const float4* Wb1 = W4 + (size_t)(g1 * 64) * 32 + u;

    size_t xb00 = ((size_t)(bg * 8 + b0) * T_) * G4_ + g0 * H_ + hg * 32 + u;
    size_t xb01 = ((size_t)(bg * 8 + b1) * T_) * G4_ + g0 * H_ + hg * 32 + u;
    size_t xb10 = ((size_t)(bg * 8 + b0) * T_) * G4_ + g1 * H_ + hg * 32 + u;
    size_t xb11 = ((size_t)(bg * 8 + b1) * T_) * G4_ + g1 * H_ + hg * 32 + u;

    // Update-phase ownership: thread (bU, uU) owns c-state of one (batch, unit).
    int bU = tid >> 5, uU = tid & 31;
    int gb = bg * 8 + bU;
    int col = hg * 32 + uU;
    float cst = 0.f;

    int phase = 0;
    for (int t = 0; t < T_; t++) {
        // Stage h_{t-1} for our 8 batches (bypass L1: written by other SMs).
        const float4* hsrc = ((const float4*)g_h) + (size_t)(phase * B_ + bg * 8) * (H_ / 4);
        float4 h0r = __ldcg(hsrc + tid);
        float4 h1r = __ldcg(hsrc + tid + 256);
        size_t toff = (size_t)t * G4_;
        float x00 = __ldg(&g_xg[xb00 + toff]);
        float x01 = __ldg(&g_xg[xb01 + toff]);
        float x10 = __ldg(&g_xg[xb10 + toff]);
        float x11 = __ldg(&g_xg[xb11 + toff]);
        Hsm4[tid] = h0r;
        Hsm4[tid + 256] = h1r;
        __syncthreads();

        float a00 = 0.f, a01 = 0.f, a10 = 0.f, a11 = 0.f;
        const float4* Ha = Hsm4 + b0 * 64;
        const float4* Hb = Hsm4 + b1 * 64;
#pragma unroll 8
        for (int k4 = 0; k4 < 64; k4++) {
            float4 w0 = Wb0[(size_t)k4 * 32];
            float4 w1 = Wb1[(size_t)k4 * 32];
            float4 ha = Ha[k4];
            float4 hb = Hb[k4];
            a00 = fmaf(w0.x, ha.x, a00); a00 = fmaf(w0.y, ha.y, a00);
            a00 = fmaf(w0.z, ha.z, a00); a00 = fmaf(w0.w, ha.w, a00);
            a01 = fmaf(w0.x, hb.x, a01); a01 = fmaf(w0.y, hb.y, a01);
            a01 = fmaf(w0.z, hb.z, a01); a01 = fmaf(w0.w, hb.w, a01);
            a10 = fmaf(w1.x, ha.x, a10); a10 = fmaf(w1.y, ha.y, a10);
            a10 = fmaf(w1.z, ha.z, a10); a10 = fmaf(w1.w, ha.w, a10);
            a11 = fmaf(w1.x, hb.x, a11); a11 = fmaf(w1.y, hb.y, a11);
            a11 = fmaf(w1.z, hb.z, a11); a11 = fmaf(w1.w, hb.w, a11);
        }
        Gsm[(b0 * 4 + g0) * 32 + u] = a00 + x00;
        Gsm[(b1 * 4 + g0) * 32 + u] = a01 + x01;
        Gsm[(b0 * 4 + g1) * 32 + u] = a10 + x10;
        Gsm[(b1 * 4 + g1) * 32 + u] = a11 + x11;
        __syncthreads();

        // LSTM cell update (torch gate order i, f, g, o)
        float gi_ = Gsm[(bU * 4 + 0) * 32 + uU];
        float gf  = Gsm[(bU * 4 + 1) * 32 + uU];
        float gc  = Gsm[(bU * 4 + 2) * 32 + uU];
        float go  = Gsm[(bU * 4 + 3) * 32 + uU];
        cst = sigm(gf) * cst + sigm(gi_) * tanhf(gc);
        float hv = sigm(go) * tanhf(cst);
        g_h[(size_t)((phase ^ 1) * B_ + gb) * H_ + col] = hv;
        g_hs[((size_t)gb * T_ + t) * H_ + col] = hv;

        // Grid barrier (release stores, arrive, spin)
        __threadfence();
        __syncthreads();
        if (tid == 0) {
            atomicAdd(&g_bar, 1u);
            unsigned target = (unsigned)(t + 1) * gridDim.x;
            while (*((volatile unsigned*)&g_bar) < target) { }
            __threadfence();
        }
        __syncthreads();
        phase ^= 1;
    }
}

// ---------------------------------------------------------------------------
// Launcher
// ---------------------------------------------------------------------------
extern "C" void kernel_launch(void* const* d_in, const int* in_sizes, int n_in,
                              void* d_out, int out_size)
{
    (void)in_sizes; (void)n_in; (void)out_size;
    const float* enc     = (const float*)d_in[0];
    const int*   sep     = (const int*)d_in[1];
    const int*   pos     = (const int*)d_in[2];
    const int*   length  = (const int*)d_in[3];
    const float* pos_emb = (const float*)d_in[4];
    const float* wl_emb  = (const float*)d_in[5];
    const float* fc_W    = (const float*)d_in[6];
    const float* fc_b    = (const float*)d_in[7];
    const float* W_ih    = (const float*)d_in[8];
    const float* W_hh    = (const float*)d_in[9];
    const float* b_ih    = (const float*)d_in[10];
    const float* b_hh    = (const float*)d_in[11];
    const float* comb    = (const float*)d_in[12];
    float* out = (float*)d_out;

    cudaFuncSetAttribute(lstm_kernel, cudaFuncAttributeMaxDynamicSharedMemorySize,
                         LSTM_SMEM_BYTES);

    feats_kernel<<<B_, H2_>>>(enc, sep, pos, pos_emb, wl_emb);
    gemm_fc<<<dim3(M_ / 64, 4), 256>>>(fc_W, fc_b);
    gemm_ih<<<dim3(M_ / 64, G4_ / 64), 256>>>(W_ih, b_ih, b_hh);
    init_kernel<<<(B_ * H_ + 255) / 256, 256>>>();
    lstm_kernel<<<128, 256, LSTM_SMEM_BYTES>>>(W_hh);
    gemm_out<<<dim3(M_ / 64, 1), 256>>>(enc, comb, length, out);
}

// round 12
// speedup vs baseline: 1.1121x; 1.1121x over previous
#include <cuda_runtime.h>
#include <math.h>

// ---------------------------------------------------------------------------
// Problem dims (fixed)
// ---------------------------------------------------------------------------
static constexpr int B_  = 128;
static constexpr int T_  = 512;
static constexpr int H_  = 256;          // lstm hidden
static constexpr int H2_ = 512;          // encoder width
static constexpr int LIN_ = 200;
static constexpr int PD_ = 50, WD_ = 20;
static constexpr int F_  = PD_ + H2_ + WD_;   // 582
static constexpr int G4_ = 4 * H_;            // 1024
static constexpr int SP_ = 58;
static constexpr int KC_ = H_ + H2_;          // 768 (combine K)
static constexpr int M_  = B_ * T_;           // 65536

// ---------------------------------------------------------------------------
// Scratch (device globals: no allocations allowed)
// ---------------------------------------------------------------------------
__device__ float g_feats[(size_t)M_ * F_];    // [B*T, 582]
__device__ float g_z[(size_t)M_ * LIN_];      // [B*T, 200]
__device__ float g_xg[(size_t)M_ * G4_];      // [B*T, 1024]  z@W_ih^T + b_ih + b_hh
__device__ float g_hs[(size_t)M_ * H_];       // [B*T, 256]   LSTM outputs
__device__ float g_h[2 * B_ * H_];            // double-buffered h state
__device__ unsigned g_bars[16 * 32];          // per-group barrier counters (1 line apart)

// ---------------------------------------------------------------------------
// 1) Feature construction: streaming per-batch scan.
// ---------------------------------------------------------------------------
__global__ void feats_kernel(const float* __restrict__ enc, const int* __restrict__ sep,
                             const int* __restrict__ pos, const float* __restrict__ pemb,
                             const float* __restrict__ wemb)
{
    int b = blockIdx.x;
    int c = threadIdx.x;                 // 0..511
    float S = 0.f, snap = 0.f;           // csum[t], csum[last_sep]
    int last_sep = 0;
    int lp = pos[b * T_];                // pos_ids[b, last_sep=0]
    for (int t = 0; t < T_; t++) {
        int wlen = t - last_sep;
        int ws = wlen < 1 ? 1 : wlen;
        int wid = ws > 7 ? 7 : ws;
        float inv = 1.f / (float)ws;
        size_t base = ((size_t)b * T_ + t) * F_;
        g_feats[base + PD_ + c] = (S - snap) * inv;                // word_avg
        if (c < PD_) g_feats[base + c] = pemb[lp * PD_ + c];       // pos emb
        if (c < WD_) g_feats[base + PD_ + H2_ + c] = wemb[wid * WD_ + c];
        int sm = sep[b * T_ + t];
        if (sm) { snap = S; last_sep = t; lp = pos[b * T_ + t]; }
        S += enc[((size_t)b * T_ + t) * H2_ + c];
    }
}

// ---------------------------------------------------------------------------
// 128x128x16 fp32 GEMM-NT, 256 threads, 8x8 micro-tile.
// A [M,K] row-major, B [N,K] row-major. Row pitch 132 floats = 528 B keeps
// every 8-float operand slice 16B-aligned (LDS.128).
// ---------------------------------------------------------------------------
__global__ __launch_bounds__(256, 1) void gemm_fc(const float* __restrict__ W,
                                                  const float* __restrict__ bias)
{
    __shared__ float As[16][132];
    __shared__ float Bs[16][132];
    int m0 = blockIdx.x * 128;
    int n0 = blockIdx.y * 128;
    int tid = threadIdx.x;
    int tx = tid & 15, ty = tid >> 4;
    float acc[8][8] = {};
    for (int k0 = 0; k0 < F_; k0 += 16) {
#pragma unroll
        for (int p = 0; p < 8; p++) {
            int e = tid + p * 256;
            int kk = e & 15, mm = e >> 4;       // mm: 0..127
            int k = k0 + kk;
            As[kk][mm] = (k < F_) ? g_feats[(size_t)(m0 + mm) * F_ + k] : 0.f;
            int n = n0 + mm;
            Bs[kk][mm] = (n < LIN_ && k < F_) ? W[(size_t)n * F_ + k] : 0.f;
        }
        __syncthreads();
#pragma unroll
        for (int kk = 0; kk < 16; kk++) {
            float a[8], bb[8];
#pragma unroll
            for (int i = 0; i < 8; i++) a[i] = As[kk][ty * 8 + i];
#pragma unroll
            for (int j = 0; j < 8; j++) bb[j] = Bs[kk][tx * 8 + j];
#pragma unroll
            for (int i = 0; i < 8; i++)
#pragma unroll
                for (int j = 0; j < 8; j++)
                    acc[i][j] = fmaf(a[i], bb[j], acc[i][j]);
        }
        __syncthreads();
    }
#pragma unroll
    for (int i = 0; i < 8; i++) {
        int m = m0 + ty * 8 + i;
        int t = m & (T_ - 1);
#pragma unroll
        for (int j = 0; j < 8; j++) {
            int n = n0 + tx * 8 + j;
            if (n < LIN_) {
                float v = (t == 0) ? 0.f : tanhf(acc[i][j] + bias[n]);
                g_z[(size_t)m * LIN_ + n] = v;
            }
        }
    }
}

__global__ __launch_bounds__(256, 1) void gemm_ih(const float* __restrict__ W,
                                                  const float* __restrict__ bih,
                                                  const float* __restrict__ bhh)
{
    __shared__ float As[16][132];
    __shared__ float Bs[16][132];
    int m0 = blockIdx.x * 128;
    int n0 = blockIdx.y * 128;
    int tid = threadIdx.x;
    int tx = tid & 15, ty = tid >> 4;
    float acc[8][8] = {};
    for (int k0 = 0; k0 < LIN_; k0 += 16) {
#pragma unroll
        for (int p = 0; p < 8; p++) {
            int e = tid + p * 256;
            int kk = e & 15, mm = e >> 4;
            int k = k0 + kk;
            As[kk][mm] = (k < LIN_) ? g_z[(size_t)(m0 + mm) * LIN_ + k] : 0.f;
            int n = n0 + mm;                    // N=1024, always in range
            Bs[kk][mm] = (k < LIN_) ? W[(size_t)n * LIN_ + k] : 0.f;
        }
        __syncthreads();
#pragma unroll
        for (int kk = 0; kk < 16; kk++) {
            float a[8], bb[8];
#pragma unroll
            for (int i = 0; i < 8; i++) a[i] = As[kk][ty * 8 + i];
#pragma unroll
            for (int j = 0; j < 8; j++) bb[j] = Bs[kk][tx * 8 + j];
#pragma unroll
            for (int i = 0; i < 8; i++)
#pragma unroll
                for (int j = 0; j < 8; j++)
                    acc[i][j] = fmaf(a[i], bb[j], acc[i][j]);
        }
        __syncthreads();
    }
#pragma unroll
    for (int i = 0; i < 8; i++) {
        int m = m0 + ty * 8 + i;
#pragma unroll
        for (int j = 0; j < 8; j++) {
            int n = n0 + tx * 8 + j;
            g_xg[(size_t)m * G4_ + n] = acc[i][j] + bih[n] + bhh[n];
        }
    }
}

// ---------------------------------------------------------------------------
// Combine projection: 64x64x16 tiles (N=58 < 64), 4x4 micro-tile. Small cost.
// ---------------------------------------------------------------------------
__global__ __launch_bounds__(256) void gemm_out(const float* __restrict__ enc,
                                                const float* __restrict__ Wc,
                                                const int* __restrict__ length,
                                                float* __restrict__ out)
{
    __shared__ float As[16][65];
    __shared__ float Bs[16][65];
    int m0 = blockIdx.x * 64;
    int tid = threadIdx.x;
    int tx = tid & 15, ty = tid >> 4;
    float acc[4][4] = {};
    for (int k0 = 0; k0 < KC_; k0 += 16) {
#pragma unroll
        for (int i = 0; i < 4; i++) {
            int e = tid + i * 256;
            int mm = e >> 4, kk = e & 15;
            int k = k0 + kk;
            int m = m0 + mm;
            float av;
            if (k < H_) av = g_hs[(size_t)m * H_ + k];
            else        av = enc[(size_t)m * H2_ + (k - H_)];
            As[kk][mm] = av;
            Bs[kk][mm] = (mm < SP_) ? Wc[(size_t)mm * KC_ + k] : 0.f;
        }
        __syncthreads();
#pragma unroll
        for (int kk = 0; kk < 16; kk++) {
            float a[4], bb[4];
#pragma unroll
            for (int i = 0; i < 4; i++) a[i] = As[kk][ty * 4 + i];
#pragma unroll
            for (int j = 0; j < 4; j++) bb[j] = Bs[kk][tx * 4 + j];
#pragma unroll
            for (int i = 0; i < 4; i++)
#pragma unroll
                for (int j = 0; j < 4; j++)
                    acc[i][j] = fmaf(a[i], bb[j], acc[i][j]);
        }
        __syncthreads();
    }
#pragma unroll
    for (int i = 0; i < 4; i++) {
        int m = m0 + ty * 4 + i;
        int b = m >> 9;
        int t = m & 511;
        int L = length[b];
#pragma unroll
        for (int j = 0; j < 4; j++) {
            int n = tx * 4 + j;
            if (n < SP_) {
                float v = acc[i][j];
                if (t == 0 && n == 0) v = -1e30f;   // forbid APP at t=0
                if (t >= L) v = 0.f;                // pad steps
                out[(size_t)m * SP_ + n] = v;
            }
        }
    }
}

// ---------------------------------------------------------------------------
// Init: zero h0 buffer and all group barrier counters (every replay).
// ---------------------------------------------------------------------------
__global__ void init_kernel()
{
    int i = blockIdx.x * blockDim.x + threadIdx.x;
    if (i < B_ * H_) g_h[i] = 0.f;
    if (i < 16 * 32) g_bars[i] = 0u;
}

// ---------------------------------------------------------------------------
// LSTM recurrence: 128 grid-resident CTAs x 256 threads.
// CTA (bg, hg): 8 batches x 32 hidden units. Data dependency is ONLY within a
// bg-group (8 CTAs produce/consume the same 8 batches' h), so each group syncs
// on its own counter — no global straggler coupling, 16x less atomic pressure.
// 143KB smem => 1 CTA/SM, grid 128 <= 148 SMs => all co-resident, no deadlock.
// ---------------------------------------------------------------------------
static constexpr int LSTM_SMEM_FLOATS = 4 * 32 * 256 + 8 * 256 + 8 * 4 * 32; // 35840
static constexpr int LSTM_SMEM_BYTES  = LSTM_SMEM_FLOATS * 4;                // 143360

__device__ __forceinline__ float sigm(float x) { return 1.f / (1.f + expf(-x)); }

__global__ __launch_bounds__(256, 1) void lstm_kernel(const float* __restrict__ Whh)
{
    extern __shared__ float smx[];
    float* Wint = smx;                         // 32768 floats (4g x 64k4 x 32u x 4)
    float* Hsm  = smx + 4 * 32 * 256;          // 2048 floats  (8b x 256)
    float* Gsm  = Hsm + 8 * 256;               // 1024 floats  (8b x 4g x 32u)
    float4* Hsm4 = (float4*)Hsm;
    const float4* W4 = (const float4*)Wint;

    int cid = blockIdx.x;
    int bg = cid >> 3;        // 0..15 (8 batches each)
    int hg = cid & 7;         // 0..7  (32 units each)
    int tid = threadIdx.x;
    int u  = tid & 31;
    int bp = (tid >> 5) & 3;  // batch pair
    int gp = tid >> 7;        // gate pair: 0 -> {i,f}, 1 -> {g,o}
    volatile unsigned* bar = (volatile unsigned*)&g_bars[bg * 32];

    // Stage W_hh slice into smem, float4-interleaved over k.
    for (int e = tid; e < 4 * 32 * 256; e += 256) {
        int g = e >> 13;
        int rem = e & 8191;
        int u2 = rem >> 8;
        int k = rem & 255;
        int row = g * H_ + hg * 32 + u2;
        Wint[((g * 64 + (k >> 2)) * 32 + u2) * 4 + (k & 3)] = Whh[(size_t)row * H_ + k];
    }
    __syncthreads();

    int g0 = 2 * gp, g1 = g0 + 1;
    int b0 = 2 * bp, b1 = b0 + 1;
    const float4* Wb0 = W4 + (size_t)(g0 * 64) * 32 + u;
    const float4* Wb1 = W4 + (size_t)(g1 * 64) * 32 + u;

    size_t xb00 = ((size_t)(bg * 8 + b0) * T_) * G4_ + g0 * H_ + hg * 32 + u;
    size_t xb01 = ((size_t)(bg * 8 + b1) * T_) * G4_ + g0 * H_ + hg * 32 + u;
    size_t xb10 = ((size_t)(bg * 8 + b0) * T_) * G4_ + g1 * H_ + hg * 32 + u;
    size_t xb11 = ((size_t)(bg * 8 + b1) * T_) * G4_ + g1 * H_ + hg * 32 + u;

    // Update-phase ownership: thread (bU, uU) owns c-state of one (batch, unit).
    int bU = tid >> 5, uU = tid & 31;
    int gb = bg * 8 + bU;
    int col = hg * 32 + uU;
    float cst = 0.f;

    int phase = 0;
    for (int t = 0; t < T_; t++) {
        // Stage h_{t-1} for our 8 batches (bypass L1: written by other SMs).
        const float4* hsrc = ((const float4*)g_h) + (size_t)(phase * B_ + bg * 8) * (H_ / 4);
        float4 h0r = __ldcg(hsrc + tid);
        float4 h1r = __ldcg(hsrc + tid + 256);
        size_t toff = (size_t)t * G4_;
        float x00 = __ldg(&g_xg[xb00 + toff]);
        float x01 = __ldg(&g_xg[xb01 + toff]);
        float x10 = __ldg(&g_xg[xb10 + toff]);
        float x11 = __ldg(&g_xg[xb11 + toff]);
        Hsm4[tid] = h0r;
        Hsm4[tid + 256] = h1r;
        __syncthreads();

        float a00 = 0.f, a01 = 0.f, a10 = 0.f, a11 = 0.f;
        const float4* Ha = Hsm4 + b0 * 64;
        const float4* Hb = Hsm4 + b1 * 64;
#pragma unroll 8
        for (int k4 = 0; k4 < 64; k4++) {
            float4 w0 = Wb0[(size_t)k4 * 32];
            float4 w1 = Wb1[(size_t)k4 * 32];
            float4 ha = Ha[k4];
            float4 hb = Hb[k4];
            a00 = fmaf(w0.x, ha.x, a00); a00 = fmaf(w0.y, ha.y, a00);
            a00 = fmaf(w0.z, ha.z, a00); a00 = fmaf(w0.w, ha.w, a00);
            a01 = fmaf(w0.x, hb.x, a01); a01 = fmaf(w0.y, hb.y, a01);
            a01 = fmaf(w0.z, hb.z, a01); a01 = fmaf(w0.w, hb.w, a01);
            a10 = fmaf(w1.x, ha.x, a10); a10 = fmaf(w1.y, ha.y, a10);
            a10 = fmaf(w1.z, ha.z, a10); a10 = fmaf(w1.w, ha.w, a10);
            a11 = fmaf(w1.x, hb.x, a11); a11 = fmaf(w1.y, hb.y, a11);
            a11 = fmaf(w1.z, hb.z, a11); a11 = fmaf(w1.w, hb.w, a11);
        }
        Gsm[(b0 * 4 + g0) * 32 + u] = a00 + x00;
        Gsm[(b1 * 4 + g0) * 32 + u] = a01 + x01;
        Gsm[(b0 * 4 + g1) * 32 + u] = a10 + x10;
        Gsm[(b1 * 4 + g1) * 32 + u] = a11 + x11;
        __syncthreads();

        // LSTM cell update (torch gate order i, f, g, o)
        float gi_ = Gsm[(bU * 4 + 0) * 32 + uU];
        float gf  = Gsm[(bU * 4 + 1) * 32 + uU];
        float gc  = Gsm[(bU * 4 + 2) * 32 + uU];
        float go  = Gsm[(bU * 4 + 3) * 32 + uU];
        cst = sigm(gf) * cst + sigm(gi_) * tanhf(gc);
        float hv = sigm(go) * tanhf(cst);
        g_h[(size_t)((phase ^ 1) * B_ + gb) * H_ + col] = hv;
        g_hs[((size_t)gb * T_ + t) * H_ + col] = hv;

        // Per-group barrier: only the 8 CTAs of this bg-group must sync.
        __threadfence();
        __syncthreads();
        if (tid == 0) {
            atomicAdd((unsigned*)bar, 1u);
            unsigned target = (unsigned)(t + 1) * 8u;
            while (*bar < target) { }
            __threadfence();
        }
        __syncthreads();
        phase ^= 1;
    }
}

// ---------------------------------------------------------------------------
// Launcher
// ---------------------------------------------------------------------------
extern "C" void kernel_launch(void* const* d_in, const int* in_sizes, int n_in,
                              void* d_out, int out_size)
{
    (void)in_sizes; (void)n_in; (void)out_size;
    const float* enc     = (const float*)d_in[0];
    const int*   sep     = (const int*)d_in[1];
    const int*   pos     = (const int*)d_in[2];
    const int*   length  = (const int*)d_in[3];
    const float* pos_emb = (const float*)d_in[4];
    const float* wl_emb  = (const float*)d_in[5];
    const float* fc_W    = (const float*)d_in[6];
    const float* fc_b    = (const float*)d_in[7];
    const float* W_ih    = (const float*)d_in[8];
    const float* W_hh    = (const float*)d_in[9];
    const float* b_ih    = (const float*)d_in[10];
    const float* b_hh    = (const float*)d_in[11];
    const float* comb    = (const float*)d_in[12];
    float* out = (float*)d_out;

    cudaFuncSetAttribute(lstm_kernel, cudaFuncAttributeMaxDynamicSharedMemorySize,
                         LSTM_SMEM_BYTES);

    feats_kernel<<<B_, H2_>>>(enc, sep, pos, pos_emb, wl_emb);
    gemm_fc<<<dim3(M_ / 128, 2), 256>>>(fc_W, fc_b);
    gemm_ih<<<dim3(M_ / 128, G4_ / 128), 256>>>(W_ih, b_ih, b_hh);
    init_kernel<<<(B_ * H_ + 255) / 256, 256>>>();
    lstm_kernel<<<128, 256, LSTM_SMEM_BYTES>>>(W_hh);
    gemm_out<<<dim3(M_ / 64, 1), 256>>>(enc, comb, length, out);
}

// round 14
// speedup vs baseline: 1.1581x; 1.0414x over previous
#include <cuda_runtime.h>
#include <math.h>

// ---------------------------------------------------------------------------
// Problem dims (fixed)
// ---------------------------------------------------------------------------
static constexpr int B_  = 128;
static constexpr int T_  = 512;
static constexpr int H_  = 256;          // lstm hidden
static constexpr int H2_ = 512;          // encoder width
static constexpr int LIN_ = 200;
static constexpr int PD_ = 50, WD_ = 20;
static constexpr int F_  = PD_ + H2_ + WD_;   // 582
static constexpr int G4_ = 4 * H_;            // 1024
static constexpr int SP_ = 58;
static constexpr int KC_ = H_ + H2_;          // 768 (combine K)
static constexpr int M_  = B_ * T_;           // 65536

// ---------------------------------------------------------------------------
// Scratch (device globals: no allocations allowed)
// ---------------------------------------------------------------------------
__device__ float g_feats[(size_t)M_ * F_];    // [B*T, 582]
__device__ float g_z[(size_t)M_ * LIN_];      // [B*T, 200]
__device__ float g_xg[(size_t)M_ * G4_];      // [B*T, 1024]  z@W_ih^T + b_ih + b_hh
__device__ float g_hs[(size_t)M_ * H_];       // [B*T, 256]   LSTM outputs
__device__ float g_h[2 * B_ * H_];            // double-buffered h state
__device__ unsigned g_bars[16 * 32];          // per-group barrier counters (1 line apart)

// ---------------------------------------------------------------------------
// 1) Feature construction: streaming per-batch scan.
//    Also re-initializes g_h / g_bars each replay (fused former init_kernel;
//    128 blocks x 512 threads = 65536 = |g_h| exactly). Stream order puts this
//    before lstm_kernel, so the zeroing is always visible in time.
// ---------------------------------------------------------------------------
__global__ void feats_kernel(const float* __restrict__ enc, const int* __restrict__ sep,
                             const int* __restrict__ pos, const float* __restrict__ pemb,
                             const float* __restrict__ wemb)
{
    int b = blockIdx.x;
    int c = threadIdx.x;                 // 0..511
    int gid = b * H2_ + c;
    g_h[gid] = 0.f;                      // zero both h phase buffers (2*B*H = 65536)
    if (gid < 16 * 32) g_bars[gid] = 0u;

    float S = 0.f, snap = 0.f;           // csum[t], csum[last_sep]
    int last_sep = 0;
    int lp = pos[b * T_];                // pos_ids[b, last_sep=0]
    for (int t = 0; t < T_; t++) {
        int wlen = t - last_sep;
        int ws = wlen < 1 ? 1 : wlen;
        int wid = ws > 7 ? 7 : ws;
        float inv = 1.f / (float)ws;
        size_t base = ((size_t)b * T_ + t) * F_;
        g_feats[base + PD_ + c] = (S - snap) * inv;                // word_avg
        if (c < PD_) g_feats[base + c] = pemb[lp * PD_ + c];       // pos emb
        if (c < WD_) g_feats[base + PD_ + H2_ + c] = wemb[wid * WD_ + c];
        int sm = sep[b * T_ + t];
        if (sm) { snap = S; last_sep = t; lp = pos[b * T_ + t]; }
        S += enc[((size_t)b * T_ + t) * H2_ + c];
    }
}

// ---------------------------------------------------------------------------
// 128x128x16 fp32 GEMM-NT, 256 threads, 8x8 micro-tile.
// __launch_bounds__(256,2): cap regs at 128 so 2 CTAs co-reside per SM and
// one CTA's global->smem load phase hides behind the other's FFMA phase.
// ---------------------------------------------------------------------------
__global__ __launch_bounds__(256, 2) void gemm_fc(const float* __restrict__ W,
                                                  const float* __restrict__ bias)
{
    __shared__ float As[16][132];
    __shared__ float Bs[16][132];
    int m0 = blockIdx.x * 128;
    int n0 = blockIdx.y * 128;
    int tid = threadIdx.x;
    int tx = tid & 15, ty = tid >> 4;
    float acc[8][8] = {};
    for (int k0 = 0; k0 < F_; k0 += 16) {
#pragma unroll
        for (int p = 0; p < 8; p++) {
            int e = tid + p * 256;
            int kk = e & 15, mm = e >> 4;       // mm: 0..127
            int k = k0 + kk;
            As[kk][mm] = (k < F_) ? g_feats[(size_t)(m0 + mm) * F_ + k] : 0.f;
            int n = n0 + mm;
            Bs[kk][mm] = (n < LIN_ && k < F_) ? W[(size_t)n * F_ + k] : 0.f;
        }
        __syncthreads();
#pragma unroll
        for (int kk = 0; kk < 16; kk++) {
            float a[8], bb[8];
#pragma unroll
            for (int i = 0; i < 8; i++) a[i] = As[kk][ty * 8 + i];
#pragma unroll
            for (int j = 0; j < 8; j++) bb[j] = Bs[kk][tx * 8 + j];
#pragma unroll
            for (int i = 0; i < 8; i++)
#pragma unroll
                for (int j = 0; j < 8; j++)
                    acc[i][j] = fmaf(a[i], bb[j], acc[i][j]);
        }
        __syncthreads();
    }
#pragma unroll
    for (int i = 0; i < 8; i++) {
        int m = m0 + ty * 8 + i;
        int t = m & (T_ - 1);
#pragma unroll
        for (int j = 0; j < 8; j++) {
            int n = n0 + tx * 8 + j;
            if (n < LIN_) {
                float v = (t == 0) ? 0.f : tanhf(acc[i][j] + bias[n]);
                g_z[(size_t)m * LIN_ + n] = v;
            }
        }
    }
}

__global__ __launch_bounds__(256, 2) void gemm_ih(const float* __restrict__ W,
                                                  const float* __restrict__ bih,
                                                  const float* __restrict__ bhh)
{
    __shared__ float As[16][132];
    __shared__ float Bs[16][132];
    int m0 = blockIdx.x * 128;
    int n0 = blockIdx.y * 128;
    int tid = threadIdx.x;
    int tx = tid & 15, ty = tid >> 4;
    float acc[8][8] = {};
    for (int k0 = 0; k0 < LIN_; k0 += 16) {
#pragma unroll
        for (int p = 0; p < 8; p++) {
            int e = tid + p * 256;
            int kk = e & 15, mm = e >> 4;
            int k = k0 + kk;
            As[kk][mm] = (k < LIN_) ? g_z[(size_t)(m0 + mm) * LIN_ + k] : 0.f;
            int n = n0 + mm;                    // N=1024, always in range
            Bs[kk][mm] = (k < LIN_) ? W[(size_t)n * LIN_ + k] : 0.f;
        }
        __syncthreads();
#pragma unroll
        for (int kk = 0; kk < 16; kk++) {
            float a[8], bb[8];
#pragma unroll
            for (int i = 0; i < 8; i++) a[i] = As[kk][ty * 8 + i];
#pragma unroll
            for (int j = 0; j < 8; j++) bb[j] = Bs[kk][tx * 8 + j];
#pragma unroll
            for (int i = 0; i < 8; i++)
#pragma unroll
                for (int j = 0; j < 8; j++)
                    acc[i][j] = fmaf(a[i], bb[j], acc[i][j]);
        }
        __syncthreads();
    }
#pragma unroll
    for (int i = 0; i < 8; i++) {
        int m = m0 + ty * 8 + i;
#pragma unroll
        for (int j = 0; j < 8; j++) {
            int n = n0 + tx * 8 + j;
            g_xg[(size_t)m * G4_ + n] = acc[i][j] + bih[n] + bhh[n];
        }
    }
}

// ---------------------------------------------------------------------------
// Combine projection: 64x64x16 tiles (N=58 < 64), 4x4 micro-tile. Small cost.
// ---------------------------------------------------------------------------
__global__ __launch_bounds__(256) void gemm_out(const float* __restrict__ enc,
                                                const float* __restrict__ Wc,
                                                const int* __restrict__ length,
                                                float* __restrict__ out)
{
    __shared__ float As[16][65];
    __shared__ float Bs[16][65];
    int m0 = blockIdx.x * 64;
    int tid = threadIdx.x;
    int tx = tid & 15, ty = tid >> 4;
    float acc[4][4] = {};
    for (int k0 = 0; k0 < KC_; k0 += 16) {
#pragma unroll
        for (int i = 0; i < 4; i++) {
            int e = tid + i * 256;
            int mm = e >> 4, kk = e & 15;
            int k = k0 + kk;
            int m = m0 + mm;
            float av;
            if (k < H_) av = g_hs[(size_t)m * H_ + k];
            else        av = enc[(size_t)m * H2_ + (k - H_)];
            As[kk][mm] = av;
            Bs[kk][mm] = (mm < SP_) ? Wc[(size_t)mm * KC_ + k] : 0.f;
        }
        __syncthreads();
#pragma unroll
        for (int kk = 0; kk < 16; kk++) {
            float a[4], bb[4];
#pragma unroll
            for (int i = 0; i < 4; i++) a[i] = As[kk][ty * 4 + i];
#pragma unroll
            for (int j = 0; j < 4; j++) bb[j] = Bs[kk][tx * 4 + j];
#pragma unroll
            for (int i = 0; i < 4; i++)
#pragma unroll
                for (int j = 0; j < 4; j++)
                    acc[i][j] = fmaf(a[i], bb[j], acc[i][j]);
        }
        __syncthreads();
    }
#pragma unroll
    for (int i = 0; i < 4; i++) {
        int m = m0 + ty * 4 + i;
        int b = m >> 9;
        int t = m & 511;
        int L = length[b];
#pragma unroll
        for (int j = 0; j < 4; j++) {
            int n = tx * 4 + j;
            if (n < SP_) {
                float v = acc[i][j];
                if (t == 0 && n == 0) v = -1e30f;   // forbid APP at t=0
                if (t >= L) v = 0.f;                // pad steps
                out[(size_t)m * SP_ + n] = v;
            }
        }
    }
}

// ---------------------------------------------------------------------------
// LSTM recurrence: 128 grid-resident CTAs x 256 threads.
// CTA (bg, hg): 8 batches x 32 hidden units; per-bg-group barriers.
// 143KB smem => 1 CTA/SM, grid 128 <= 148 SMs => all co-resident, no deadlock.
// ---------------------------------------------------------------------------
static constexpr int LSTM_SMEM_FLOATS = 4 * 32 * 256 + 8 * 256 + 8 * 4 * 32; // 35840
static constexpr int LSTM_SMEM_BYTES  = LSTM_SMEM_FLOATS * 4;                // 143360

__device__ __forceinline__ float sigm(float x) { return 1.f / (1.f + expf(-x)); }

__global__ __launch_bounds__(256, 1) void lstm_kernel(const float* __restrict__ Whh)
{
    extern __shared__ float smx[];
    float* Wint = smx;                         // 32768 floats (4g x 64k4 x 32u x 4)
    float* Hsm  = smx + 4 * 32 * 256;          // 2048 floats  (8b x 256)
    float* Gsm  = Hsm + 8 * 256;               // 1024 floats  (8b x 4g x 32u)
    float4* Hsm4 = (float4*)Hsm;
    const float4* W4 = (const float4*)Wint;

    int cid = blockIdx.x;
    int bg = cid >> 3;        // 0..15 (8 batches each)
    int hg = cid & 7;         // 0..7  (32 units each)
    int tid = threadIdx.x;
    int u  = tid & 31;
    int bp = (tid >> 5) & 3;  // batch pair
    int gp = tid >> 7;        // gate pair: 0 -> {i,f}, 1 -> {g,o}
    volatile unsigned* bar = (volatile unsigned*)&g_bars[bg * 32];

    // Stage W_hh slice into smem, float4-interleaved over k.
    for (int e = tid; e < 4 * 32 * 256; e += 256) {
        int g = e >> 13;
        int rem = e & 8191;
        int u2 = rem >> 8;
        int k = rem & 255;
        int row = g * H_ + hg * 32 + u2;
        Wint[((g * 64 + (k >> 2)) * 32 + u2) * 4 + (k & 3)] = Whh[(size_t)row * H_ + k];
    }
    __syncthreads();

    int g0 = 2 * gp, g1 = g0 + 1;
    int b0 = 2 * bp, b1 = b0 + 1;
    const float4* Wb0 = W4 + (size_t)(g0 * 64) * 32 + u;
    const float4* Wb1 = W4 + (size_t)(g1 * 64) * 32 + u;

    size_t xb00 = ((size_t)(bg * 8 + b0) * T_) * G4_ + g0 * H_ + hg * 32 + u;
    size_t xb01 = ((size_t)(bg * 8 + b1) * T_) * G4_ + g0 * H_ + hg * 32 + u;
    size_t xb10 = ((size_t)(bg * 8 + b0) * T_) * G4_ + g1 * H_ + hg * 32 + u;
    size_t xb11 = ((size_t)(bg * 8 + b1) * T_) * G4_ + g1 * H_ + hg * 32 + u;

    // Update-phase ownership: thread (bU, uU) owns c-state of one (batch, unit).
    int bU = tid >> 5, uU = tid & 31;
    int gb = bg * 8 + bU;
    int col = hg * 32 + uU;
    float cst = 0.f;

    int phase = 0;
    for (int t = 0; t < T_; t++) {
        // Stage h_{t-1} for our 8 batches (bypass L1: written by other SMs).
        const float4* hsrc = ((const float4*)g_h) + (size_t)(phase * B_ + bg * 8) * (H_ / 4);
        float4 h0r = __ldcg(hsrc + tid);
        float4 h1r = __ldcg(hsrc + tid + 256);
        size_t toff = (size_t)t * G4_;
        float x00 = __ldg(&g_xg[xb00 + toff]);
        float x01 = __ldg(&g_xg[xb01 + toff]);
        float x10 = __ldg(&g_xg[xb10 + toff]);
        float x11 = __ldg(&g_xg[xb11 + toff]);
        Hsm4[tid] = h0r;
        Hsm4[tid + 256] = h1r;
        __syncthreads();

        float a00 = 0.f, a01 = 0.f, a10 = 0.f, a11 = 0.f;
        const float4* Ha = Hsm4 + b0 * 64;
        const float4* Hb = Hsm4 + b1 * 64;
#pragma unroll 8
        for (int k4 = 0; k4 < 64; k4++) {
            float4 w0 = Wb0[(size_t)k4 * 32];
            float4 w1 = Wb1[(size_t)k4 * 32];
            float4 ha = Ha[k4];
            float4 hb = Hb[k4];
            a00 = fmaf(w0.x, ha.x, a00); a00 = fmaf(w0.y, ha.y, a00);
            a00 = fmaf(w0.z, ha.z, a00); a00 = fmaf(w0.w, ha.w, a00);
            a01 = fmaf(w0.x, hb.x, a01); a01 = fmaf(w0.y, hb.y, a01);
            a01 = fmaf(w0.z, hb.z, a01); a01 = fmaf(w0.w, hb.w, a01);
            a10 = fmaf(w1.x, ha.x, a10); a10 = fmaf(w1.y, ha.y, a10);
            a10 = fmaf(w1.z, ha.z, a10); a10 = fmaf(w1.w, ha.w, a10);
            a11 = fmaf(w1.x, hb.x, a11); a11 = fmaf(w1.y, hb.y, a11);
            a11 = fmaf(w1.z, hb.z, a11); a11 = fmaf(w1.w, hb.w, a11);
        }
        Gsm[(b0 * 4 + g0) * 32 + u] = a00 + x00;
        Gsm[(b1 * 4 + g0) * 32 + u] = a01 + x01;
        Gsm[(b0 * 4 + g1) * 32 + u] = a10 + x10;
        Gsm[(b1 * 4 + g1) * 32 + u] = a11 + x11;
        __syncthreads();

        // LSTM cell update (torch gate order i, f, g, o)
        float gi_ = Gsm[(bU * 4 + 0) * 32 + uU];
        float gf  = Gsm[(bU * 4 + 1) * 32 + uU];
        float gc  = Gsm[(bU * 4 + 2) * 32 + uU];
        float go  = Gsm[(bU * 4 + 3) * 32 + uU];
        cst = sigm(gf) * cst + sigm(gi_) * tanhf(gc);
        float hv = sigm(go) * tanhf(cst);
        g_h[(size_t)((phase ^ 1) * B_ + gb) * H_ + col] = hv;
        g_hs[((size_t)gb * T_ + t) * H_ + col] = hv;

        // Per-group barrier: only the 8 CTAs of this bg-group must sync.
        __threadfence();
        __syncthreads();
        if (tid == 0) {
            atomicAdd((unsigned*)bar, 1u);
            unsigned target = (unsigned)(t + 1) * 8u;
            while (*bar < target) { }
            __threadfence();
        }
        __syncthreads();
        phase ^= 1;
    }
}

// ---------------------------------------------------------------------------
// Launcher. Order puts lstm_kernel at our 4th launch — the slot ncu's
// "-s 5 -c 1" has been capturing (it hit init_kernel at slot 4 in R8/R12).
// ---------------------------------------------------------------------------
extern "C" void kernel_launch(void* const* d_in, const int* in_sizes, int n_in,
                              void* d_out, int out_size)
{
    (void)in_sizes; (void)n_in; (void)out_size;
    const float* enc     = (const float*)d_in[0];
    const int*   sep     = (const int*)d_in[1];
    const int*   pos     = (const int*)d_in[2];
    const int*   length  = (const int*)d_in[3];
    const float* pos_emb = (const float*)d_in[4];
    const float* wl_emb  = (const float*)d_in[5];
    const float* fc_W    = (const float*)d_in[6];
    const float* fc_b    = (const float*)d_in[7];
    const float* W_ih    = (const float*)d_in[8];
    const float* W_hh    = (const float*)d_in[9];
    const float* b_ih    = (const float*)d_in[10];
    const float* b_hh    = (const float*)d_in[11];
    const float* comb    = (const float*)d_in[12];
    float* out = (float*)d_out;

    cudaFuncSetAttribute(lstm_kernel, cudaFuncAttributeMaxDynamicSharedMemorySize,
                         LSTM_SMEM_BYTES);

    feats_kernel<<<B_, H2_>>>(enc, sep, pos, pos_emb, wl_emb);   // also inits g_h/g_bars
    gemm_fc<<<dim3(M_ / 128, 2), 256>>>(fc_W, fc_b);
    gemm_ih<<<dim3(M_ / 128, G4_ / 128), 256>>>(W_ih, b_ih, b_hh);
    lstm_kernel<<<128, 256, LSTM_SMEM_BYTES>>>(W_hh);
    gemm_out<<<dim3(M_ / 64, 1), 256>>>(enc, comb, length, out);
}

// round 17
// speedup vs baseline: 1.4614x; 1.2619x over previous
#include <cuda_runtime.h>
#include <cuda_bf16.h>
#include <math.h>
#include <stdint.h>

// ---------------------------------------------------------------------------
// Problem dims (fixed)
// ---------------------------------------------------------------------------
static constexpr int B_  = 128;
static constexpr int T_  = 512;
static constexpr int H_  = 256;          // lstm hidden
static constexpr int H2_ = 512;          // encoder width
static constexpr int LIN_ = 200;
static constexpr int PD_ = 50, WD_ = 20;
static constexpr int F_  = PD_ + H2_ + WD_;   // 582
static constexpr int G4_ = 4 * H_;            // 1024
static constexpr int SP_ = 58;
static constexpr int KC_ = H_ + H2_;          // 768 (combine K)
static constexpr int M_  = B_ * T_;           // 65536

// ---------------------------------------------------------------------------
// Scratch (device globals: no allocations allowed)
// ---------------------------------------------------------------------------
__device__ float g_feats[(size_t)M_ * F_];    // [B*T, 582]
__device__ float g_z[(size_t)M_ * LIN_];      // [B*T, 200]
__device__ float g_xg[(size_t)M_ * G4_];      // [B*T, 1024]
__device__ float g_hs[(size_t)M_ * H_];       // [B*T, 256]
__device__ float g_h[2 * B_ * H_];            // double-buffered h state
__device__ unsigned g_bars[16 * 32];          // per-group barrier counters

// ---------------------------------------------------------------------------
// mma.sync helpers (bf16 m16n8k16, fp32 accum) — sm_80+ fragment layouts.
// A (row-major 16x16): ldmatrix.x4, addr lanes: rows (lane&15), k-off 8*(lane>>4)
//   -> r0..r3 = a0..a3 exactly per PTX fragment table.
// B ([N][K] row-major == col-major KxN): ldmatrix.x2 NON-trans, addr lanes:
//   n-rows (lane&7), k-off 8*((lane>>3)&1) -> lane gets (n=lane>>2, k=2*(lane&3))
//   pairs = PTX b0/b1 layout.
// D: d0=(r=l>>2, c=2*(l&3)), d1=c+1, d2=r+8, d3=r+8,c+1.
// ---------------------------------------------------------------------------
__device__ __forceinline__ uint32_t smem_u32(const void* p) {
    return (uint32_t)__cvta_generic_to_shared(p);
}
__device__ __forceinline__ void ldsm4(uint32_t& r0, uint32_t& r1, uint32_t& r2,
                                      uint32_t& r3, uint32_t a) {
    asm volatile("ldmatrix.sync.aligned.m8n8.x4.shared.b16 {%0,%1,%2,%3}, [%4];"
                 : "=r"(r0), "=r"(r1), "=r"(r2), "=r"(r3) : "r"(a));
}
__device__ __forceinline__ void ldsm2(uint32_t& r0, uint32_t& r1, uint32_t a) {
    asm volatile("ldmatrix.sync.aligned.m8n8.x2.shared.b16 {%0,%1}, [%2];"
                 : "=r"(r0), "=r"(r1) : "r"(a));
}
__device__ __forceinline__ void mma16816(float* c, uint32_t a0, uint32_t a1,
                                         uint32_t a2, uint32_t a3,
                                         uint32_t b0, uint32_t b1) {
    asm volatile(
        "mma.sync.aligned.m16n8k16.row.col.f32.bf16.bf16.f32 "
        "{%0,%1,%2,%3}, {%4,%5,%6,%7}, {%8,%9}, {%0,%1,%2,%3};"
        : "+f"(c[0]), "+f"(c[1]), "+f"(c[2]), "+f"(c[3])
        : "r"(a0), "r"(a1), "r"(a2), "r"(a3), "r"(b0), "r"(b1));
}

// Tile config shared by the three mma GEMMs.
static constexpr int BM = 128, BN = 64, BK = 64;
static constexpr int KP = BK + 8;       // bf16 row pitch: 144 B, 16B-aligned, conflict-free

// ---------------------------------------------------------------------------
// feats: streaming per-batch scan + re-init of g_h / g_bars each replay.
// ---------------------------------------------------------------------------
__global__ void feats_kernel(const float* __restrict__ enc, const int* __restrict__ sep,
                             const int* __restrict__ pos, const float* __restrict__ pemb,
                             const float* __restrict__ wemb)
{
    int b = blockIdx.x;
    int c = threadIdx.x;                 // 0..511
    int gid = b * H2_ + c;
    g_h[gid] = 0.f;                      // 128*512 = 65536 = |g_h|
    if (gid < 16 * 32) g_bars[gid] = 0u;

    float S = 0.f, snap = 0.f;
    int last_sep = 0;
    int lp = pos[b * T_];
    for (int t = 0; t < T_; t++) {
        int wlen = t - last_sep;
        int ws = wlen < 1 ? 1 : wlen;
        int wid = ws > 7 ? 7 : ws;
        float inv = 1.f / (float)ws;
        size_t base = ((size_t)b * T_ + t) * F_;
        g_feats[base + PD_ + c] = (S - snap) * inv;
        if (c < PD_) g_feats[base + c] = pemb[lp * PD_ + c];
        if (c < WD_) g_feats[base + PD_ + H2_ + c] = wemb[wid * WD_ + c];
        int sm = sep[b * T_ + t];
        if (sm) { snap = S; last_sep = t; lp = pos[b * T_ + t]; }
        S += enc[((size_t)b * T_ + t) * H2_ + c];
    }
}

// ---------------------------------------------------------------------------
// FC GEMM: g_z = tanh(feats @ fc_W^T + b); K=582 (10 chunks), N=200 (grid.y=4)
// ---------------------------------------------------------------------------
__global__ __launch_bounds__(256) void gemm_fc(const float* __restrict__ W,
                                               const float* __restrict__ bias)
{
    __shared__ __align__(16) __nv_bfloat16 As[BM * KP];
    __shared__ __align__(16) __nv_bfloat16 Bs[BN * KP];
    int tid = threadIdx.x, lane = tid & 31, wid = tid >> 5;
    int wm = wid >> 1, wn = wid & 1;
    int m0 = blockIdx.x * BM, n0 = blockIdx.y * BN;
    float acc[2][4][4] = {};

    for (int ch = 0; ch < 10; ch++) {
        int k0g = ch * BK;
#pragma unroll
        for (int i = 0; i < BM * BK / 256; i++) {
            int e = tid + i * 256; int mm = e >> 6, kk = e & 63; int k = k0g + kk;
            float v = (k < F_) ? g_feats[(size_t)(m0 + mm) * F_ + k] : 0.f;
            As[mm * KP + kk] = __float2bfloat16(v);
        }
#pragma unroll
        for (int i = 0; i < BN * BK / 256; i++) {
            int e = tid + i * 256; int nn = e >> 6, kk = e & 63; int k = k0g + kk;
            int n = n0 + nn;
            float v = (n < LIN_ && k < F_) ? W[(size_t)n * F_ + k] : 0.f;
            Bs[nn * KP + kk] = __float2bfloat16(v);
        }
        __syncthreads();
#pragma unroll
        for (int ks = 0; ks < BK / 16; ks++) {
            int k0 = ks * 16;
            uint32_t a[2][4];
#pragma unroll
            for (int mi = 0; mi < 2; mi++) {
                int row = wm * 32 + mi * 16 + (lane & 15);
                ldsm4(a[mi][0], a[mi][1], a[mi][2], a[mi][3],
                      smem_u32(&As[row * KP + k0 + 8 * (lane >> 4)]));
            }
#pragma unroll
            for (int ni = 0; ni < 4; ni++) {
                int brow = wn * 32 + ni * 8 + (lane & 7);
                uint32_t b0, b1;
                ldsm2(b0, b1, smem_u32(&Bs[brow * KP + k0 + 8 * ((lane >> 3) & 1)]));
#pragma unroll
                for (int mi = 0; mi < 2; mi++)
                    mma16816(acc[mi][ni], a[mi][0], a[mi][1], a[mi][2], a[mi][3], b0, b1);
            }
        }
        __syncthreads();
    }
#pragma unroll
    for (int mi = 0; mi < 2; mi++)
#pragma unroll
        for (int ni = 0; ni < 4; ni++) {
            int r0 = m0 + wm * 32 + mi * 16 + (lane >> 2);
            int c0 = n0 + wn * 32 + ni * 8 + 2 * (lane & 3);
#pragma unroll
            for (int e = 0; e < 4; e++) {
                int m = r0 + (e >> 1) * 8;
                int n = c0 + (e & 1);
                if (n < LIN_) {
                    int t = m & (T_ - 1);
                    float v = (t == 0) ? 0.f : tanhf(acc[mi][ni][e] + bias[n]);
                    g_z[(size_t)m * LIN_ + n] = v;
                }
            }
        }
}

// ---------------------------------------------------------------------------
// IH GEMM: g_xg = z @ W_ih^T + b_ih + b_hh; K=200 (4 chunks), N=1024 (grid.y=16)
// ---------------------------------------------------------------------------
__global__ __launch_bounds__(256) void gemm_ih(const float* __restrict__ W,
                                               const float* __restrict__ bih,
                                               const float* __restrict__ bhh)
{
    __shared__ __align__(16) __nv_bfloat16 As[BM * KP];
    __shared__ __align__(16) __nv_bfloat16 Bs[BN * KP];
    int tid = threadIdx.x, lane = tid & 31, wid = tid >> 5;
    int wm = wid >> 1, wn = wid & 1;
    int m0 = blockIdx.x * BM, n0 = blockIdx.y * BN;
    float acc[2][4][4] = {};

    for (int ch = 0; ch < 4; ch++) {
        int k0g = ch * BK;
#pragma unroll
        for (int i = 0; i < BM * BK / 256; i++) {
            int e = tid + i * 256; int mm = e >> 6, kk = e & 63; int k = k0g + kk;
            float v = (k < LIN_) ? g_z[(size_t)(m0 + mm) * LIN_ + k] : 0.f;
            As[mm * KP + kk] = __float2bfloat16(v);
        }
#pragma unroll
        for (int i = 0; i < BN * BK / 256; i++) {
            int e = tid + i * 256; int nn = e >> 6, kk = e & 63; int k = k0g + kk;
            int n = n0 + nn;   // N=1024 exact
            float v = (k < LIN_) ? W[(size_t)n * LIN_ + k] : 0.f;
            Bs[nn * KP + kk] = __float2bfloat16(v);
        }
        __syncthreads();
#pragma unroll
        for (int ks = 0; ks < BK / 16; ks++) {
            int k0 = ks * 16;
            uint32_t a[2][4];
#pragma unroll
            for (int mi = 0; mi < 2; mi++) {
                int row = wm * 32 + mi * 16 + (lane & 15);
                ldsm4(a[mi][0], a[mi][1], a[mi][2], a[mi][3],
                      smem_u32(&As[row * KP + k0 + 8 * (lane >> 4)]));
            }
#pragma unroll
            for (int ni = 0; ni < 4; ni++) {
                int brow = wn * 32 + ni * 8 + (lane & 7);
                uint32_t b0, b1;
                ldsm2(b0, b1, smem_u32(&Bs[brow * KP + k0 + 8 * ((lane >> 3) & 1)]));
#pragma unroll
                for (int mi = 0; mi < 2; mi++)
                    mma16816(acc[mi][ni], a[mi][0], a[mi][1], a[mi][2], a[mi][3], b0, b1);
            }
        }
        __syncthreads();
    }
#pragma unroll
    for (int mi = 0; mi < 2; mi++)
#pragma unroll
        for (int ni = 0; ni < 4; ni++) {
            int r0 = m0 + wm * 32 + mi * 16 + (lane >> 2);
            int c0 = n0 + wn * 32 + ni * 8 + 2 * (lane & 3);
#pragma unroll
            for (int e = 0; e < 4; e++) {
                int m = r0 + (e >> 1) * 8;
                int n = c0 + (e & 1);
                g_xg[(size_t)m * G4_ + n] = acc[mi][ni][e] + bih[n] + bhh[n];
            }
        }
}

// ---------------------------------------------------------------------------
// OUT GEMM: logits = [hs, enc] @ Wc^T; K=768 (12 chunks), N=58 (one 64-tile)
// ---------------------------------------------------------------------------
__global__ __launch_bounds__(256) void gemm_out(const float* __restrict__ enc,
                                                const float* __restrict__ Wc,
                                                const int* __restrict__ length,
                                                float* __restrict__ out)
{
    __shared__ __align__(16) __nv_bfloat16 As[BM * KP];
    __shared__ __align__(16) __nv_bfloat16 Bs[BN * KP];
    int tid = threadIdx.x, lane = tid & 31, wid = tid >> 5;
    int wm = wid >> 1, wn = wid & 1;
    int m0 = blockIdx.x * BM, n0 = 0;
    float acc[2][4][4] = {};

    for (int ch = 0; ch < 12; ch++) {
        int k0g = ch * BK;
#pragma unroll
        for (int i = 0; i < BM * BK / 256; i++) {
            int e = tid + i * 256; int mm = e >> 6, kk = e & 63; int k = k0g + kk;
            int m = m0 + mm;
            float v = (k < H_) ? g_hs[(size_t)m * H_ + k]
                               : enc[(size_t)m * H2_ + (k - H_)];   // K=768 exact
            As[mm * KP + kk] = __float2bfloat16(v);
        }
#pragma unroll
        for (int i = 0; i < BN * BK / 256; i++) {
            int e = tid + i * 256; int nn = e >> 6, kk = e & 63; int k = k0g + kk;
            float v = (nn < SP_) ? Wc[(size_t)nn * KC_ + k] : 0.f;
            Bs[nn * KP + kk] = __float2bfloat16(v);
        }
        __syncthreads();
#pragma unroll
        for (int ks = 0; ks < BK / 16; ks++) {
            int k0 = ks * 16;
            uint32_t a[2][4];
#pragma unroll
            for (int mi = 0; mi < 2; mi++) {
                int row = wm * 32 + mi * 16 + (lane & 15);
                ldsm4(a[mi][0], a[mi][1], a[mi][2], a[mi][3],
                      smem_u32(&As[row * KP + k0 + 8 * (lane >> 4)]));
            }
#pragma unroll
            for (int ni = 0; ni < 4; ni++) {
                int brow = wn * 32 + ni * 8 + (lane & 7);
                uint32_t b0, b1;
                ldsm2(b0, b1, smem_u32(&Bs[brow * KP + k0 + 8 * ((lane >> 3) & 1)]));
#pragma unroll
                for (int mi = 0; mi < 2; mi++)
                    mma16816(acc[mi][ni], a[mi][0], a[mi][1], a[mi][2], a[mi][3], b0, b1);
            }
        }
        __syncthreads();
    }
#pragma unroll
    for (int mi = 0; mi < 2; mi++)
#pragma unroll
        for (int ni = 0; ni < 4; ni++) {
            int r0 = m0 + wm * 32 + mi * 16 + (lane >> 2);
            int c0 = n0 + wn * 32 + ni * 8 + 2 * (lane & 3);
#pragma unroll
            for (int e = 0; e < 4; e++) {
                int m = r0 + (e >> 1) * 8;
                int n = c0 + (e & 1);
                if (n < SP_) {
                    int b = m >> 9;
                    int t = m & 511;
                    int L = length[b];
                    float v = acc[mi][ni][e];
                    if (t == 0 && n == 0) v = -1e30f;
                    if (t >= L) v = 0.f;
                    out[(size_t)m * SP_ + n] = v;
                }
            }
        }
}

// ---------------------------------------------------------------------------
// LSTM recurrence (unchanged from R14): 128 grid-resident CTAs x 256 threads,
// per-bg-group barriers, co-resident (143KB smem => 1 CTA/SM, 128 <= 148).
// ---------------------------------------------------------------------------
static constexpr int LSTM_SMEM_FLOATS = 4 * 32 * 256 + 8 * 256 + 8 * 4 * 32; // 35840
static constexpr int LSTM_SMEM_BYTES  = LSTM_SMEM_FLOATS * 4;                // 143360

__device__ __forceinline__ float sigm(float x) { return 1.f / (1.f + expf(-x)); }

__global__ __launch_bounds__(256, 1) void lstm_kernel(const float* __restrict__ Whh)
{
    extern __shared__ float smx[];
    float* Wint = smx;
    float* Hsm  = smx + 4 * 32 * 256;
    float* Gsm  = Hsm + 8 * 256;
    float4* Hsm4 = (float4*)Hsm;
    const float4* W4 = (const float4*)Wint;

    int cid = blockIdx.x;
    int bg = cid >> 3;
    int hg = cid & 7;
    int tid = threadIdx.x;
    int u  = tid & 31;
    int bp = (tid >> 5) & 3;
    int gp = tid >> 7;
    volatile unsigned* bar = (volatile unsigned*)&g_bars[bg * 32];

    for (int e = tid; e < 4 * 32 * 256; e += 256) {
        int g = e >> 13;
        int rem = e & 8191;
        int u2 = rem >> 8;
        int k = rem & 255;
        int row = g * H_ + hg * 32 + u2;
        Wint[((g * 64 + (k >> 2)) * 32 + u2) * 4 + (k & 3)] = Whh[(size_t)row * H_ + k];
    }
    __syncthreads();

    int g0 = 2 * gp, g1 = g0 + 1;
    int b0 = 2 * bp, b1 = b0 + 1;
    const float4* Wb0 = W4 + (size_t)(g0 * 64) * 32 + u;
    const float4* Wb1 = W4 + (size_t)(g1 * 64) * 32 + u;

    size_t xb00 = ((size_t)(bg * 8 + b0) * T_) * G4_ + g0 * H_ + hg * 32 + u;
    size_t xb01 = ((size_t)(bg * 8 + b1) * T_) * G4_ + g0 * H_ + hg * 32 + u;
    size_t xb10 = ((size_t)(bg * 8 + b0) * T_) * G4_ + g1 * H_ + hg * 32 + u;
    size_t xb11 = ((size_t)(bg * 8 + b1) * T_) * G4_ + g1 * H_ + hg * 32 + u;

    int bU = tid >> 5, uU = tid & 31;
    int gb = bg * 8 + bU;
    int col = hg * 32 + uU;
    float cst = 0.f;

    int phase = 0;
    for (int t = 0; t < T_; t++) {
        const float4* hsrc = ((const float4*)g_h) + (size_t)(phase * B_ + bg * 8) * (H_ / 4);
        float4 h0r = __ldcg(hsrc + tid);
        float4 h1r = __ldcg(hsrc + tid + 256);
        size_t toff = (size_t)t * G4_;
        float x00 = __ldg(&g_xg[xb00 + toff]);
        float x01 = __ldg(&g_xg[xb01 + toff]);
        float x10 = __ldg(&g_xg[xb10 + toff]);
        float x11 = __ldg(&g_xg[xb11 + toff]);
        Hsm4[tid] = h0r;
        Hsm4[tid + 256] = h1r;
        __syncthreads();

        float a00 = 0.f, a01 = 0.f, a10 = 0.f, a11 = 0.f;
        const float4* Ha = Hsm4 + b0 * 64;
        const float4* Hb = Hsm4 + b1 * 64;
#pragma unroll 8
        for (int k4 = 0; k4 < 64; k4++) {
            float4 w0 = Wb0[(size_t)k4 * 32];
            float4 w1 = Wb1[(size_t)k4 * 32];
            float4 ha = Ha[k4];
            float4 hb = Hb[k4];
            a00 = fmaf(w0.x, ha.x, a00); a00 = fmaf(w0.y, ha.y, a00);
            a00 = fmaf(w0.z, ha.z, a00); a00 = fmaf(w0.w, ha.w, a00);
            a01 = fmaf(w0.x, hb.x, a01); a01 = fmaf(w0.y, hb.y, a01);
            a01 = fmaf(w0.z, hb.z, a01); a01 = fmaf(w0.w, hb.w, a01);
            a10 = fmaf(w1.x, ha.x, a10); a10 = fmaf(w1.y, ha.y, a10);
            a10 = fmaf(w1.z, ha.z, a10); a10 = fmaf(w1.w, ha.w, a10);
            a11 = fmaf(w1.x, hb.x, a11); a11 = fmaf(w1.y, hb.y, a11);
            a11 = fmaf(w1.z, hb.z, a11); a11 = fmaf(w1.w, hb.w, a11);
        }
        Gsm[(b0 * 4 + g0) * 32 + u] = a00 + x00;
        Gsm[(b1 * 4 + g0) * 32 + u] = a01 + x01;
        Gsm[(b0 * 4 + g1) * 32 + u] = a10 + x10;
        Gsm[(b1 * 4 + g1) * 32 + u] = a11 + x11;
        __syncthreads();

        float gi_ = Gsm[(bU * 4 + 0) * 32 + uU];
        float gf  = Gsm[(bU * 4 + 1) * 32 + uU];
        float gc  = Gsm[(bU * 4 + 2) * 32 + uU];
        float go  = Gsm[(bU * 4 + 3) * 32 + uU];
        cst = sigm(gf) * cst + sigm(gi_) * tanhf(gc);
        float hv = sigm(go) * tanhf(cst);
        g_h[(size_t)((phase ^ 1) * B_ + gb) * H_ + col] = hv;
        g_hs[((size_t)gb * T_ + t) * H_ + col] = hv;

        __threadfence();
        __syncthreads();
        if (tid == 0) {
            atomicAdd((unsigned*)bar, 1u);
            unsigned target = (unsigned)(t + 1) * 8u;
            while (*bar < target) { }
            __threadfence();
        }
        __syncthreads();
        phase ^= 1;
    }
}

// ---------------------------------------------------------------------------
// Launcher (lstm stays at launch slot 4 for the profiler).
// ---------------------------------------------------------------------------
extern "C" void kernel_launch(void* const* d_in, const int* in_sizes, int n_in,
                              void* d_out, int out_size)
{
    (void)in_sizes; (void)n_in; (void)out_size;
    const float* enc     = (const float*)d_in[0];
    const int*   sep     = (const int*)d_in[1];
    const int*   pos     = (const int*)d_in[2];
    const int*   length  = (const int*)d_in[3];
    const float* pos_emb = (const float*)d_in[4];
    const float* wl_emb  = (const float*)d_in[5];
    const float* fc_W    = (const float*)d_in[6];
    const float* fc_b    = (const float*)d_in[7];
    const float* W_ih    = (const float*)d_in[8];
    const float* W_hh    = (const float*)d_in[9];
    const float* b_ih    = (const float*)d_in[10];
    const float* b_hh    = (const float*)d_in[11];
    const float* comb    = (const float*)d_in[12];
    float* out = (float*)d_out;

    cudaFuncSetAttribute(lstm_kernel, cudaFuncAttributeMaxDynamicSharedMemorySize,
                         LSTM_SMEM_BYTES);

    feats_kernel<<<B_, H2_>>>(enc, sep, pos, pos_emb, wl_emb);   // also inits g_h/g_bars
    gemm_fc<<<dim3(M_ / BM, 4), 256>>>(fc_W, fc_b);              // N=200 -> 4 tiles
    gemm_ih<<<dim3(M_ / BM, G4_ / BN), 256>>>(W_ih, b_ih, b_hh); // N=1024 -> 16 tiles
    lstm_kernel<<<128, 256, LSTM_SMEM_BYTES>>>(W_hh);
    gemm_out<<<dim3(M_ / BM, 1), 256>>>(enc, comb, length, out); // N=58 -> 1 tile
}